// round 15
// baseline (speedup 1.0000x reference)
#include <cuda_runtime.h>
#include <cuda_bf16.h>
#include <math.h>

// Problem constants
#define C 144
#define W 77
#define KW 10
#define FC 64
#define CONV_OUT 68                  // W - KW + 1
#define FC_N (C*FC)                  // 9216
#define CONCAT_N (FC_N + CONV_OUT)   // 9284
#define CONCAT_V4 (CONCAT_N/4)       // 2321
#define H2 128
#define SPLIT 4
#define CHUNK 581                    // ceil(2321/4)

#define NB_FC 144
#define NB_CV 4                      // 4 blocks x 17 conv outputs
#define NB_PROD (NB_FC + NB_CV)      // 148
#define NB_CONS (H2 * SPLIT)         // 512
#define GRID (NB_PROD + NB_CONS)     // 660  (< 5*148=740 resident => no deadlock)

// Scratch (no allocations allowed)
__device__ __align__(16) float g_concat[CONCAT_N];
__device__ float g_part[H2 * SPLIT];
__device__ int g_prod_done;
__device__ int g_done;

__device__ __forceinline__ float warp_reduce(float v) {
    #pragma unroll
    for (int o = 16; o > 0; o >>= 1) v += __shfl_xor_sync(0xffffffffu, v, o);
    return v;
}

__global__ __launch_bounds__(256, 5) void fused_pc(
    const float* __restrict__ x,       // [C, W]
    const float* __restrict__ fc_w,    // [C*FC, W]
    const float* __restrict__ fc_b,    // [C*FC]
    const float* __restrict__ conv_w,  // [C*KW]
    const float* __restrict__ conv_b,  // [1]
    const float* __restrict__ w2,      // [H2, CONCAT_N]
    const float* __restrict__ b2,      // [H2]
    const float* __restrict__ w3,      // [H2]
    const float* __restrict__ b3,      // [1]
    float* __restrict__ out)           // [1]
{
    const int b = blockIdx.x;
    const int tid = threadIdx.x;
    const int warp = tid >> 5, lane = tid & 31;

    __shared__ float red[8];
    __shared__ float hv[H2];
    __shared__ int is_last;

    if (b < NB_FC) {
        // ---------- FC producer: channel b, 8 warps x 8 outputs ----------
        __shared__ float xs[W];
        if (tid < W) xs[tid] = x[b * W + tid];
        __syncthreads();

        #pragma unroll
        for (int i = 0; i < 8; i++) {
            const int o = b * FC + warp * 8 + i;
            const float* __restrict__ wr = fc_w + (size_t)o * W;
            float s = wr[lane] * xs[lane] + wr[lane + 32] * xs[lane + 32];
            if (lane < 13) s += wr[lane + 64] * xs[lane + 64];
            s = warp_reduce(s);
            if (lane == 0) g_concat[o] = s + fc_b[o];
        }
        __syncthreads();
        if (tid == 0) {
            __threadfence();
            atomicAdd(&g_prod_done, 1);
        }
    } else if (b < NB_PROD) {
        // ---------- Conv producer: 17 outputs ----------
        const int obase = (b - NB_FC) * 17;
        for (int oo = warp; oo < 17; oo += 8) {
            const int o = obase + oo;
            float s = 0.f;
            int c = lane / KW, k = lane - (lane / KW) * KW;
            #pragma unroll
            for (int it = 0; it < 45; it++) {        // i = lane + 32*it over 1440
                s += conv_w[c * KW + k] * x[c * W + o + k];
                k += 2; c += 3;
                if (k >= KW) { k -= KW; c += 1; }
            }
            s = warp_reduce(s);
            if (lane == 0) g_concat[FC_N + o] = s + conv_b[0];
        }
        __syncthreads();
        if (tid == 0) {
            __threadfence();
            atomicAdd(&g_prod_done, 1);
        }
    } else {
        // ---------- Consumer: row j, chunk sp ----------
        const int blk = b - NB_PROD;
        const int j  = blk >> 2;
        const int sp = blk & 3;
        const int start = sp * CHUNK;
        const int end = (start + CHUNK < CONCAT_V4) ? start + CHUNK : CONCAT_V4;
        const int i0 = start + tid;
        const bool v2 = (i0 + 512 < end);            // i0, i0+256 always valid

        const float4* __restrict__ wrow =
            reinterpret_cast<const float4*>(w2 + (size_t)j * CONCAT_N);

        // Prefetch w2 into registers: independent of producers, overlaps them.
        const float4 w0 = wrow[i0];
        const float4 w1 = wrow[i0 + 256];
        float4 wv2 = make_float4(0.f, 0.f, 0.f, 0.f);
        if (v2) wv2 = wrow[i0 + 512];

        // One-sided wait for all producers.
        if (tid == 0) {
            while (*(volatile int*)&g_prod_done < NB_PROD) __nanosleep(32);
            __threadfence();
        }
        __syncthreads();

        const float4* __restrict__ cc = reinterpret_cast<const float4*>(g_concat);
        const float4 c0 = cc[i0];
        const float4 c1 = cc[i0 + 256];
        float s = w0.x*c0.x + w0.y*c0.y + w0.z*c0.z + w0.w*c0.w
                + w1.x*c1.x + w1.y*c1.y + w1.z*c1.z + w1.w*c1.w;
        if (v2) {
            const float4 c2 = cc[i0 + 512];
            s += wv2.x*c2.x + wv2.y*c2.y + wv2.z*c2.z + wv2.w*c2.w;
        }
        s = warp_reduce(s);
        if (lane == 0) red[warp] = s;
        __syncthreads();
        if (tid == 0) {
            float t = red[0];
            #pragma unroll
            for (int q = 1; q < 8; q++) t += red[q];
            g_part[j * SPLIT + sp] = t;
        }
    }

    // ---------- Completion detection (all 660 blocks) ----------
    __syncthreads();
    if (tid == 0) {
        __threadfence();
        const int n = atomicAdd(&g_done, 1);
        is_last = (n == GRID - 1) ? 1 : 0;
    }
    __syncthreads();

    // ---------- Tail: bias+relu over 128, head, reset (last block only) ----------
    if (is_last) {
        __threadfence();
        if (tid < H2) {
            const float v = g_part[tid * SPLIT + 0] + g_part[tid * SPLIT + 1]
                          + g_part[tid * SPLIT + 2] + g_part[tid * SPLIT + 3];
            hv[tid] = fmaxf(v + b2[tid], 0.f);
        }
        __syncthreads();
        if (warp == 0) {
            float acc = 0.f;
            #pragma unroll
            for (int q = 0; q < 4; q++) {
                const int r = lane + q * 32;
                acc += w3[r] * hv[r];
            }
            acc = warp_reduce(acc);
            if (lane == 0) {
                acc = fmaxf(acc + b3[0], 0.f);
                out[0] = 1.f / (1.f + expf(-acc));
                g_prod_done = 0;       // reset for next graph replay
                g_done = 0;
            }
        }
    }
}

extern "C" void kernel_launch(void* const* d_in, const int* in_sizes, int n_in,
                              void* d_out, int out_size) {
    const float* x      = (const float*)d_in[0];
    const float* fc_w   = (const float*)d_in[1];
    const float* fc_b   = (const float*)d_in[2];
    const float* conv_w = (const float*)d_in[3];
    const float* conv_b = (const float*)d_in[4];
    const float* w2     = (const float*)d_in[5];
    const float* b2     = (const float*)d_in[6];
    const float* w3     = (const float*)d_in[7];
    const float* b3     = (const float*)d_in[8];
    float* out = (float*)d_out;

    fused_pc<<<GRID, 256>>>(x, fc_w, fc_b, conv_w, conv_b, w2, b2, w3, b3, out);
}